// round 1
// baseline (speedup 1.0000x reference)
#include <cuda_runtime.h>
#include <math.h>

#define S_LEN   4096
#define HID     1280
#define H3      3840
#define NH      16
#define HD      80
#define NSEQ    8
#define SCALE   0.11180339887498949f   // 1/sqrt(80)

// ---------------- scratch (device globals; no allocations allowed) ----------
__device__ float g_qkv[(size_t)S_LEN * H3];      // 62.9 MB
__device__ float g_attn[(size_t)S_LEN * HID];    // 21 MB

// ---------------- generic tiled fp32 GEMM: C = A[M,K] @ B[K,N] + bias -------
// BM=64, BN=64, BK=16, 256 threads, 4x4 microtile. M,N,K divisible by tiles.
__global__ __launch_bounds__(256) void gemm_bias_kernel(
    const float* __restrict__ A, const float* __restrict__ B,
    const float* __restrict__ bias, float* __restrict__ C,
    int K, int N)
{
    __shared__ float As[16][64];   // As[k][m]
    __shared__ float Bs[16][64];   // Bs[k][n]

    const int tid = threadIdx.x;
    const int m0 = blockIdx.y * 64;
    const int n0 = blockIdx.x * 64;

    const int tx = tid & 15;       // 0..15 -> n
    const int ty = tid >> 4;       // 0..15 -> m
    const int mt = ty * 4;
    const int nt = tx * 4;

    // A-load mapping: each thread loads float4 along K
    const int a_row = tid >> 2;          // 0..63
    const int a_k   = (tid & 3) * 4;     // 0,4,8,12
    // B-load mapping
    const int b_k   = tid >> 4;          // 0..15
    const int b_n   = (tid & 15) * 4;    // 0..60

    float c[4][4];
#pragma unroll
    for (int i = 0; i < 4; i++)
#pragma unroll
        for (int j = 0; j < 4; j++) c[i][j] = 0.f;

    for (int k0 = 0; k0 < K; k0 += 16) {
        // load A tile (transposed into As[k][m])
        float4 av = *(const float4*)(A + (size_t)(m0 + a_row) * K + k0 + a_k);
        As[a_k + 0][a_row] = av.x;
        As[a_k + 1][a_row] = av.y;
        As[a_k + 2][a_row] = av.z;
        As[a_k + 3][a_row] = av.w;
        // load B tile
        float4 bv = *(const float4*)(B + (size_t)(k0 + b_k) * N + n0 + b_n);
        *(float4*)&Bs[b_k][b_n] = bv;
        __syncthreads();

#pragma unroll
        for (int k = 0; k < 16; k++) {
            float4 a4 = *(const float4*)&As[k][mt];
            float4 b4 = *(const float4*)&Bs[k][nt];
            float ar[4] = {a4.x, a4.y, a4.z, a4.w};
            float br[4] = {b4.x, b4.y, b4.z, b4.w};
#pragma unroll
            for (int i = 0; i < 4; i++)
#pragma unroll
                for (int j = 0; j < 4; j++)
                    c[i][j] += ar[i] * br[j];
        }
        __syncthreads();
    }

    float4 bb = *(const float4*)(bias + n0 + nt);
    float bcol[4] = {bb.x, bb.y, bb.z, bb.w};
#pragma unroll
    for (int i = 0; i < 4; i++) {
        float4 o;
        o.x = c[i][0] + bcol[0];
        o.y = c[i][1] + bcol[1];
        o.z = c[i][2] + bcol[2];
        o.w = c[i][3] + bcol[3];
        *(float4*)(C + (size_t)(m0 + mt + i) * N + n0 + nt) = o;
    }
}

// ---------------- RoPE on q,k halves of qkv, in place ------------------------
__global__ void rope_kernel(float* __restrict__ qkv,
                            const float* __restrict__ cosb,
                            const float* __restrict__ sinb)
{
    const int s = blockIdx.x;
    const float* cr = cosb + (size_t)s * HD;
    const float* sr = sinb + (size_t)s * HD;
    float* row = qkv + (size_t)s * H3;

    for (int i = threadIdx.x; i < 2 * NH * (HD / 2); i += blockDim.x) {
        const int which = i / (NH * (HD / 2));        // 0 = q, 1 = k
        int j = i - which * (NH * (HD / 2));
        const int h = j / (HD / 2);
        const int d = j - h * (HD / 2);               // 0..39
        float* base = row + which * HID + h * HD;
        float a  = base[d];
        float b  = base[d + HD / 2];
        float c0 = cr[d],          s0 = sr[d];
        float c1 = cr[d + HD / 2], s1 = sr[d + HD / 2];
        base[d]          = a * c0 - b * s0;
        base[d + HD / 2] = b * c1 + a * s1;
    }
}

// ---------------- varlen flash attention ------------------------------------
// block: 128 threads, each owns one query row; grid (S/128, NH)
#define TQ 128
#define TK 64
__global__ __launch_bounds__(TQ, 2) void attn_kernel(
    const float* __restrict__ qkv, const int* __restrict__ cu,
    float* __restrict__ out)
{
    __shared__ float Ks[TK][HD];
    __shared__ float Vs[TK][HD];
    __shared__ int s_cu[NSEQ + 1];

    const int h   = blockIdx.y;
    const int qs0 = blockIdx.x * TQ;
    const int tid = threadIdx.x;
    const int s   = qs0 + tid;

    if (tid <= NSEQ) s_cu[tid] = cu[tid];
    __syncthreads();

    // per-row segment bounds
    int lo = 0, hi = S_LEN;
#pragma unroll
    for (int i = 0; i < NSEQ; i++) {
        if (s >= s_cu[i] && s < s_cu[i + 1]) { lo = s_cu[i]; hi = s_cu[i + 1]; }
    }
    // block-wide key range (rows are sorted, so first row's lo .. last row's hi)
    int blk_lo = 0, blk_hi = S_LEN;
    {
        const int s0 = qs0, s1 = qs0 + TQ - 1;
#pragma unroll
        for (int i = 0; i < NSEQ; i++) {
            if (s0 >= s_cu[i] && s0 < s_cu[i + 1]) blk_lo = s_cu[i];
            if (s1 >= s_cu[i] && s1 < s_cu[i + 1]) blk_hi = s_cu[i + 1];
        }
    }

    // q row in registers
    float q[HD];
    {
        const float* qp = qkv + (size_t)s * H3 + h * HD;
#pragma unroll
        for (int d = 0; d < HD; d += 4) {
            float4 v = *(const float4*)(qp + d);
            q[d] = v.x; q[d + 1] = v.y; q[d + 2] = v.z; q[d + 3] = v.w;
        }
    }

    float m = -INFINITY, l = 0.f;
    float acc[HD];
#pragma unroll
    for (int d = 0; d < HD; d++) acc[d] = 0.f;

    for (int t0 = blk_lo & ~(TK - 1); t0 < blk_hi; t0 += TK) {
        __syncthreads();
        // cooperative load of K and V tiles (TK x HD each)
        for (int i = tid * 4; i < TK * HD; i += TQ * 4) {
            const int t = i / HD;
            const int d = i - t * HD;
            const int tt = t0 + t;
            float4 kv = make_float4(0.f, 0.f, 0.f, 0.f);
            float4 vv = make_float4(0.f, 0.f, 0.f, 0.f);
            if (tt < S_LEN) {
                kv = *(const float4*)(qkv + (size_t)tt * H3 + HID + h * HD + d);
                vv = *(const float4*)(qkv + (size_t)tt * H3 + 2 * HID + h * HD + d);
            }
            *(float4*)&Ks[t][d] = kv;
            *(float4*)&Vs[t][d] = vv;
        }
        __syncthreads();

        const int tstart = max(t0, lo);
        const int tend   = min(t0 + TK, hi);
        for (int t = tstart; t < tend; t++) {
            const int tt = t - t0;
            float p0 = 0.f, p1 = 0.f, p2 = 0.f, p3 = 0.f;
            const float4* krow = (const float4*)Ks[tt];
#pragma unroll
            for (int j = 0; j < HD / 4; j++) {
                float4 kk = krow[j];
                p0 += q[4 * j + 0] * kk.x;
                p1 += q[4 * j + 1] * kk.y;
                p2 += q[4 * j + 2] * kk.z;
                p3 += q[4 * j + 3] * kk.w;
            }
            const float sc = ((p0 + p1) + (p2 + p3)) * SCALE;
            if (sc > m) {
                const float corr = __expf(m - sc);   // first valid key: exp(-inf)=0
                l *= corr;
#pragma unroll
                for (int d = 0; d < HD; d++) acc[d] *= corr;
                m = sc;
            }
            const float p = __expf(sc - m);
            l += p;
            const float4* vrow = (const float4*)Vs[tt];
#pragma unroll
            for (int j = 0; j < HD / 4; j++) {
                float4 vv = vrow[j];
                acc[4 * j + 0] += p * vv.x;
                acc[4 * j + 1] += p * vv.y;
                acc[4 * j + 2] += p * vv.z;
                acc[4 * j + 3] += p * vv.w;
            }
        }
    }

    const float inv = 1.f / l;
    float* op = out + (size_t)s * HID + h * HD;
#pragma unroll
    for (int d = 0; d < HD; d += 4) {
        float4 o;
        o.x = acc[d] * inv; o.y = acc[d + 1] * inv;
        o.z = acc[d + 2] * inv; o.w = acc[d + 3] * inv;
        *(float4*)(op + d) = o;
    }
}

// ---------------------------------------------------------------------------
extern "C" void kernel_launch(void* const* d_in, const int* in_sizes, int n_in,
                              void* d_out, int out_size)
{
    const float* x       = (const float*)d_in[0];
    const int*   cu      = (const int*)  d_in[1];
    const float* cosb    = (const float*)d_in[2];
    const float* sinb    = (const float*)d_in[3];
    const float* w_qkv   = (const float*)d_in[4];
    const float* b_qkv   = (const float*)d_in[5];
    const float* w_proj  = (const float*)d_in[6];
    const float* b_proj  = (const float*)d_in[7];
    float* out = (float*)d_out;

    float* qkv;  cudaGetSymbolAddress((void**)&qkv,  g_qkv);
    float* attn; cudaGetSymbolAddress((void**)&attn, g_attn);

    // 1) qkv = x @ w_qkv + b_qkv    (4096 x 1280 x 3840)
    {
        dim3 grid(H3 / 64, S_LEN / 64);
        gemm_bias_kernel<<<grid, 256>>>(x, w_qkv, b_qkv, qkv, HID, H3);
    }
    // 2) RoPE on q,k in place
    rope_kernel<<<S_LEN, 128>>>(qkv, cosb, sinb);
    // 3) varlen attention
    {
        dim3 grid(S_LEN / TQ, NH);
        attn_kernel<<<grid, TQ>>>(qkv, cu, attn);
    }
    // 4) out = attn @ w_proj + b_proj  (4096 x 1280 x 1280)
    {
        dim3 grid(HID / 64, S_LEN / 64);
        gemm_bias_kernel<<<grid, 256>>>(attn, w_proj, b_proj, out, HID, HID);
    }
}

// round 3
// speedup vs baseline: 1.8124x; 1.8124x over previous
#include <cuda_runtime.h>
#include <math.h>
#include <cstdint>

#define S_LEN   4096
#define HID     1280
#define H3      3840
#define NH      16
#define HD      80
#define NSEQ    8
#define SCALE   0.11180339887498949f   // 1/sqrt(80)

// ---------------- scratch (device globals; no allocations allowed) ----------
__device__ float g_qkv[(size_t)S_LEN * H3];          // 62.9 MB
__device__ float g_attn[(size_t)S_LEN * HID];        // 21 MB

// =================== tf32 helpers ===========================================
__device__ __forceinline__ float tf32_rna(float f) {
    uint32_t u;
    asm("cvt.rna.tf32.f32 %0, %1;" : "=r"(u) : "f"(f));
    return __uint_as_float(u);
}

__device__ __forceinline__ void mma1688(float* d,
                                        uint32_t a0, uint32_t a1, uint32_t a2, uint32_t a3,
                                        uint32_t b0, uint32_t b1) {
    asm volatile(
        "mma.sync.aligned.m16n8k8.row.col.f32.tf32.tf32.f32 "
        "{%0,%1,%2,%3}, {%4,%5,%6,%7}, {%8,%9}, {%0,%1,%2,%3};"
        : "+f"(d[0]), "+f"(d[1]), "+f"(d[2]), "+f"(d[3])
        : "r"(a0), "r"(a1), "r"(a2), "r"(a3), "r"(b0), "r"(b1));
}

// =================== tensor-core tf32 GEMM ==================================
// C[M,N] = A[M,K] @ W[K,N] + bias.   CTA tile 128x128, BK=32, 256 threads.
// Warp grid 2(M) x 4(N); warp tile 64x32 via 4x4 m16n8k8 tiles.
#define AST 36     // A smem row stride in words (32 + 4 pad)
#define BST 136    // B smem row stride in words (128 + 8 pad)
#define ABUF (128 * AST)
#define BBUF (32 * BST)
#define GEMM_SMEM ((2 * ABUF + 2 * BBUF) * 4)   // 71680 bytes

__global__ __launch_bounds__(256) void gemm_mma_kernel(
    const float* __restrict__ A, const float* __restrict__ W,
    const float* __restrict__ bias, float* __restrict__ C,
    int K, int N)
{
    extern __shared__ float smem[];
    float* sA = smem;               // 2 x ABUF
    float* sB = smem + 2 * ABUF;    // 2 x BBUF

    const int tid  = threadIdx.x;
    const int warp = tid >> 5;
    const int lane = tid & 31;
    const int wm = warp >> 2;           // 0..1
    const int wn = warp & 3;            // 0..3
    const int m0 = blockIdx.y * 128;
    const int n0 = blockIdx.x * 128;

    const int r_a   = lane >> 2;        // 0..7
    const int c_a   = lane & 3;         // 0..3
    const int q_b   = lane & 3;
    const int col_b = lane >> 2;

    // gmem loader mapping
    const int a_row = tid >> 3;         // 0..31
    const int a_col = (tid & 7) * 4;    // 0..28
    const int b_row = tid >> 5;         // 0..7
    const int b_col = (tid & 31) * 4;   // 0..124

    float c[4][4][4];
#pragma unroll
    for (int i = 0; i < 4; i++)
#pragma unroll
        for (int j = 0; j < 4; j++)
#pragma unroll
            for (int v = 0; v < 4; v++) c[i][j][v] = 0.f;

    const int NC = K / 32;
    float4 pa[4], pb[4];

    // prefetch chunk 0
#pragma unroll
    for (int i = 0; i < 4; i++) {
        pa[i] = *(const float4*)(A + (size_t)(m0 + a_row + 32 * i) * K + a_col);
        pb[i] = *(const float4*)(W + (size_t)(b_row + 8 * i) * N + n0 + b_col);
    }
    // store chunk 0 into buf 0
#pragma unroll
    for (int i = 0; i < 4; i++) {
        float4 av = pa[i];
        av.x = tf32_rna(av.x); av.y = tf32_rna(av.y);
        av.z = tf32_rna(av.z); av.w = tf32_rna(av.w);
        *(float4*)(sA + (a_row + 32 * i) * AST + a_col) = av;
        float4 bv = pb[i];
        bv.x = tf32_rna(bv.x); bv.y = tf32_rna(bv.y);
        bv.z = tf32_rna(bv.z); bv.w = tf32_rna(bv.w);
        *(float4*)(sB + (b_row + 8 * i) * BST + b_col) = bv;
    }
    __syncthreads();

    for (int ck = 0; ck < NC; ck++) {
        const int buf = ck & 1;
        // prefetch next chunk to registers
        if (ck + 1 < NC) {
            const int k0 = (ck + 1) * 32;
#pragma unroll
            for (int i = 0; i < 4; i++) {
                pa[i] = *(const float4*)(A + (size_t)(m0 + a_row + 32 * i) * K + k0 + a_col);
                pb[i] = *(const float4*)(W + (size_t)(k0 + b_row + 8 * i) * N + n0 + b_col);
            }
        }

        const float* sAc = sA + buf * ABUF;
        const float* sBc = sB + buf * BBUF;

#pragma unroll
        for (int t = 0; t < 4; t++) {
            const int kk = t * 8;
            uint32_t af[4][4], bf[4][2];
#pragma unroll
            for (int i = 0; i < 4; i++) {
                const float* ab = sAc + (wm * 64 + i * 16 + r_a) * AST + kk + c_a;
                af[i][0] = __float_as_uint(ab[0]);
                af[i][1] = __float_as_uint(ab[8 * AST]);
                af[i][2] = __float_as_uint(ab[4]);
                af[i][3] = __float_as_uint(ab[8 * AST + 4]);
            }
#pragma unroll
            for (int j = 0; j < 4; j++) {
                const float* bb = sBc + (kk + q_b) * BST + wn * 32 + j * 8 + col_b;
                bf[j][0] = __float_as_uint(bb[0]);
                bf[j][1] = __float_as_uint(bb[4 * BST]);
            }
#pragma unroll
            for (int i = 0; i < 4; i++)
#pragma unroll
                for (int j = 0; j < 4; j++)
                    mma1688(c[i][j], af[i][0], af[i][1], af[i][2], af[i][3],
                            bf[j][0], bf[j][1]);
        }

        // store next chunk into the other buffer
        if (ck + 1 < NC) {
            float* dA = sA + (buf ^ 1) * ABUF;
            float* dB = sB + (buf ^ 1) * BBUF;
#pragma unroll
            for (int i = 0; i < 4; i++) {
                float4 av = pa[i];
                av.x = tf32_rna(av.x); av.y = tf32_rna(av.y);
                av.z = tf32_rna(av.z); av.w = tf32_rna(av.w);
                *(float4*)(dA + (a_row + 32 * i) * AST + a_col) = av;
                float4 bv = pb[i];
                bv.x = tf32_rna(bv.x); bv.y = tf32_rna(bv.y);
                bv.z = tf32_rna(bv.z); bv.w = tf32_rna(bv.w);
                *(float4*)(dB + (b_row + 8 * i) * BST + b_col) = bv;
            }
        }
        __syncthreads();
    }

    // epilogue
#pragma unroll
    for (int i = 0; i < 4; i++) {
        const int row = m0 + wm * 64 + i * 16 + (lane >> 2);
#pragma unroll
        for (int j = 0; j < 4; j++) {
            const int col = n0 + wn * 32 + j * 8 + (lane & 3) * 2;
            float2 bb = *(const float2*)(bias + col);
            float2 o0, o1;
            o0.x = c[i][j][0] + bb.x;  o0.y = c[i][j][1] + bb.y;
            o1.x = c[i][j][2] + bb.x;  o1.y = c[i][j][3] + bb.y;
            *(float2*)(C + (size_t)row * N + col)       = o0;
            *(float2*)(C + (size_t)(row + 8) * N + col) = o1;
        }
    }
}

// ---------------- RoPE on q,k halves of qkv, in place ------------------------
__global__ void rope_kernel(float* __restrict__ qkv,
                            const float* __restrict__ cosb,
                            const float* __restrict__ sinb)
{
    const int s = blockIdx.x;
    const float* cr = cosb + (size_t)s * HD;
    const float* sr = sinb + (size_t)s * HD;
    float* row = qkv + (size_t)s * H3;

    for (int i = threadIdx.x; i < 2 * NH * (HD / 2); i += blockDim.x) {
        const int which = i / (NH * (HD / 2));        // 0 = q, 1 = k
        int jj = i - which * (NH * (HD / 2));
        const int h = jj / (HD / 2);
        const int d = jj - h * (HD / 2);              // 0..39
        float* base = row + which * HID + h * HD;
        float a  = base[d];
        float b  = base[d + HD / 2];
        float c0 = cr[d],          s0 = sr[d];
        float c1 = cr[d + HD / 2], s1 = sr[d + HD / 2];
        base[d]          = a * c0 - b * s0;
        base[d + HD / 2] = b * c1 + a * s1;
    }
}

// ---------------- varlen flash attention ------------------------------------
#define TQ 128
#define TK 64
__global__ __launch_bounds__(TQ, 2) void attn_kernel(
    const float* __restrict__ qkv, const int* __restrict__ cu,
    float* __restrict__ out)
{
    __shared__ float Ks[TK][HD];
    __shared__ float Vs[TK][HD];
    __shared__ int s_cu[NSEQ + 1];

    const int h   = blockIdx.y;
    const int qs0 = blockIdx.x * TQ;
    const int tid = threadIdx.x;
    const int s   = qs0 + tid;

    if (tid <= NSEQ) s_cu[tid] = cu[tid];
    __syncthreads();

    int lo = 0, hi = S_LEN;
#pragma unroll
    for (int i = 0; i < NSEQ; i++) {
        if (s >= s_cu[i] && s < s_cu[i + 1]) { lo = s_cu[i]; hi = s_cu[i + 1]; }
    }
    int blk_lo = 0, blk_hi = S_LEN;
    {
        const int s0 = qs0, s1 = qs0 + TQ - 1;
#pragma unroll
        for (int i = 0; i < NSEQ; i++) {
            if (s0 >= s_cu[i] && s0 < s_cu[i + 1]) blk_lo = s_cu[i];
            if (s1 >= s_cu[i] && s1 < s_cu[i + 1]) blk_hi = s_cu[i + 1];
        }
    }

    float q[HD];
    {
        const float* qp = qkv + (size_t)s * H3 + h * HD;
#pragma unroll
        for (int d = 0; d < HD; d += 4) {
            float4 v = *(const float4*)(qp + d);
            q[d] = v.x; q[d + 1] = v.y; q[d + 2] = v.z; q[d + 3] = v.w;
        }
    }

    float m = -INFINITY, l = 0.f;
    float acc[HD];
#pragma unroll
    for (int d = 0; d < HD; d++) acc[d] = 0.f;

    for (int t0 = blk_lo & ~(TK - 1); t0 < blk_hi; t0 += TK) {
        __syncthreads();
        for (int i = tid * 4; i < TK * HD; i += TQ * 4) {
            const int t = i / HD;
            const int d = i - t * HD;
            const int tt = t0 + t;
            float4 kv = make_float4(0.f, 0.f, 0.f, 0.f);
            float4 vv = make_float4(0.f, 0.f, 0.f, 0.f);
            if (tt < S_LEN) {
                kv = *(const float4*)(qkv + (size_t)tt * H3 + HID + h * HD + d);
                vv = *(const float4*)(qkv + (size_t)tt * H3 + 2 * HID + h * HD + d);
            }
            *(float4*)&Ks[t][d] = kv;
            *(float4*)&Vs[t][d] = vv;
        }
        __syncthreads();

        const int tstart = max(t0, lo);
        const int tend   = min(t0 + TK, hi);
        for (int t = tstart; t < tend; t++) {
            const int tt = t - t0;
            float p0 = 0.f, p1 = 0.f, p2 = 0.f, p3 = 0.f;
            const float4* krow = (const float4*)Ks[tt];
#pragma unroll
            for (int jj = 0; jj < HD / 4; jj++) {
                float4 kk = krow[jj];
                p0 += q[4 * jj + 0] * kk.x;
                p1 += q[4 * jj + 1] * kk.y;
                p2 += q[4 * jj + 2] * kk.z;
                p3 += q[4 * jj + 3] * kk.w;
            }
            const float sc = ((p0 + p1) + (p2 + p3)) * SCALE;
            if (sc > m) {
                const float corr = __expf(m - sc);
                l *= corr;
#pragma unroll
                for (int d = 0; d < HD; d++) acc[d] *= corr;
                m = sc;
            }
            const float p = __expf(sc - m);
            l += p;
            const float4* vrow = (const float4*)Vs[tt];
#pragma unroll
            for (int jj = 0; jj < HD / 4; jj++) {
                float4 vv = vrow[jj];
                acc[4 * jj + 0] += p * vv.x;
                acc[4 * jj + 1] += p * vv.y;
                acc[4 * jj + 2] += p * vv.z;
                acc[4 * jj + 3] += p * vv.w;
            }
        }
    }

    const float inv = 1.f / l;
    float* op = out + (size_t)s * HID + h * HD;
#pragma unroll
    for (int d = 0; d < HD; d += 4) {
        float4 o;
        o.x = acc[d] * inv; o.y = acc[d + 1] * inv;
        o.z = acc[d + 2] * inv; o.w = acc[d + 3] * inv;
        *(float4*)(op + d) = o;
    }
}

// ---------------------------------------------------------------------------
extern "C" void kernel_launch(void* const* d_in, const int* in_sizes, int n_in,
                              void* d_out, int out_size)
{
    const float* x       = (const float*)d_in[0];
    const int*   cu      = (const int*)  d_in[1];
    const float* cosb    = (const float*)d_in[2];
    const float* sinb    = (const float*)d_in[3];
    const float* w_qkv   = (const float*)d_in[4];
    const float* b_qkv   = (const float*)d_in[5];
    const float* w_proj  = (const float*)d_in[6];
    const float* b_proj  = (const float*)d_in[7];
    float* out = (float*)d_out;

    float* qkv;  cudaGetSymbolAddress((void**)&qkv,  g_qkv);
    float* attn; cudaGetSymbolAddress((void**)&attn, g_attn);

    cudaFuncSetAttribute(gemm_mma_kernel,
                         cudaFuncAttributeMaxDynamicSharedMemorySize, GEMM_SMEM);

    // 1) qkv = x @ w_qkv + b_qkv    (4096 x 1280 x 3840), tf32 mma.sync
    gemm_mma_kernel<<<dim3(H3 / 128, S_LEN / 128), 256, GEMM_SMEM>>>(
        x, w_qkv, b_qkv, qkv, HID, H3);
    // 2) RoPE on q,k in place
    rope_kernel<<<S_LEN, 128>>>(qkv, cosb, sinb);
    // 3) varlen attention
    attn_kernel<<<dim3(S_LEN / TQ, NH), TQ>>>(qkv, cu, attn);
    // 4) out = attn @ w_proj + b_proj  (4096 x 1280 x 1280), tf32 mma.sync
    gemm_mma_kernel<<<dim3(HID / 128, S_LEN / 128), 256, GEMM_SMEM>>>(
        attn, w_proj, b_proj, out, HID, HID);
}

// round 4
// speedup vs baseline: 3.1591x; 1.7430x over previous
#include <cuda_runtime.h>
#include <math.h>
#include <cstdint>

#define S_LEN   4096
#define HID     1280
#define H3      3840
#define NH      16
#define HD      80
#define NSEQ    8
#define SCALE   0.11180339887498949f   // 1/sqrt(80)

// ---------------- scratch (device globals; no allocations allowed) ----------
__device__ float g_qkv[(size_t)S_LEN * H3];          // 62.9 MB
__device__ float g_attn[(size_t)S_LEN * HID];        // 21 MB

// =================== tf32 helpers ===========================================
__device__ __forceinline__ float tf32_rna(float f) {
    uint32_t u;
    asm("cvt.rna.tf32.f32 %0, %1;" : "=r"(u) : "f"(f));
    return __uint_as_float(u);
}
__device__ __forceinline__ uint32_t tf32_rna_u(float f) {
    uint32_t u;
    asm("cvt.rna.tf32.f32 %0, %1;" : "=r"(u) : "f"(f));
    return u;
}

__device__ __forceinline__ void mma1688(float* d,
                                        uint32_t a0, uint32_t a1, uint32_t a2, uint32_t a3,
                                        uint32_t b0, uint32_t b1) {
    asm volatile(
        "mma.sync.aligned.m16n8k8.row.col.f32.tf32.tf32.f32 "
        "{%0,%1,%2,%3}, {%4,%5,%6,%7}, {%8,%9}, {%0,%1,%2,%3};"
        : "+f"(d[0]), "+f"(d[1]), "+f"(d[2]), "+f"(d[3])
        : "r"(a0), "r"(a1), "r"(a2), "r"(a3), "r"(b0), "r"(b1));
}

// =================== tensor-core tf32 GEMM ==================================
// C[M,N] = A[M,K] @ W[K,N] + bias.   CTA tile 128x128, BK=32, 256 threads.
#define AST 36
#define BST 136
#define ABUF (128 * AST)
#define BBUF (32 * BST)
#define GEMM_SMEM ((2 * ABUF + 2 * BBUF) * 4)

__global__ __launch_bounds__(256) void gemm_mma_kernel(
    const float* __restrict__ A, const float* __restrict__ W,
    const float* __restrict__ bias, float* __restrict__ C,
    int K, int N)
{
    extern __shared__ float smem[];
    float* sA = smem;
    float* sB = smem + 2 * ABUF;

    const int tid  = threadIdx.x;
    const int warp = tid >> 5;
    const int lane = tid & 31;
    const int wm = warp >> 2;
    const int wn = warp & 3;
    const int m0 = blockIdx.y * 128;
    const int n0 = blockIdx.x * 128;

    const int r_a   = lane >> 2;
    const int c_a   = lane & 3;
    const int q_b   = lane & 3;
    const int col_b = lane >> 2;

    const int a_row = tid >> 3;
    const int a_col = (tid & 7) * 4;
    const int b_row = tid >> 5;
    const int b_col = (tid & 31) * 4;

    float c[4][4][4];
#pragma unroll
    for (int i = 0; i < 4; i++)
#pragma unroll
        for (int j = 0; j < 4; j++)
#pragma unroll
            for (int v = 0; v < 4; v++) c[i][j][v] = 0.f;

    const int NC = K / 32;
    float4 pa[4], pb[4];

#pragma unroll
    for (int i = 0; i < 4; i++) {
        pa[i] = *(const float4*)(A + (size_t)(m0 + a_row + 32 * i) * K + a_col);
        pb[i] = *(const float4*)(W + (size_t)(b_row + 8 * i) * N + n0 + b_col);
    }
#pragma unroll
    for (int i = 0; i < 4; i++) {
        float4 av = pa[i];
        av.x = tf32_rna(av.x); av.y = tf32_rna(av.y);
        av.z = tf32_rna(av.z); av.w = tf32_rna(av.w);
        *(float4*)(sA + (a_row + 32 * i) * AST + a_col) = av;
        float4 bv = pb[i];
        bv.x = tf32_rna(bv.x); bv.y = tf32_rna(bv.y);
        bv.z = tf32_rna(bv.z); bv.w = tf32_rna(bv.w);
        *(float4*)(sB + (b_row + 8 * i) * BST + b_col) = bv;
    }
    __syncthreads();

    for (int ck = 0; ck < NC; ck++) {
        const int buf = ck & 1;
        if (ck + 1 < NC) {
            const int k0 = (ck + 1) * 32;
#pragma unroll
            for (int i = 0; i < 4; i++) {
                pa[i] = *(const float4*)(A + (size_t)(m0 + a_row + 32 * i) * K + k0 + a_col);
                pb[i] = *(const float4*)(W + (size_t)(k0 + b_row + 8 * i) * N + n0 + b_col);
            }
        }

        const float* sAc = sA + buf * ABUF;
        const float* sBc = sB + buf * BBUF;

#pragma unroll
        for (int t = 0; t < 4; t++) {
            const int kk = t * 8;
            uint32_t af[4][4], bf[4][2];
#pragma unroll
            for (int i = 0; i < 4; i++) {
                const float* ab = sAc + (wm * 64 + i * 16 + r_a) * AST + kk + c_a;
                af[i][0] = __float_as_uint(ab[0]);
                af[i][1] = __float_as_uint(ab[8 * AST]);
                af[i][2] = __float_as_uint(ab[4]);
                af[i][3] = __float_as_uint(ab[8 * AST + 4]);
            }
#pragma unroll
            for (int j = 0; j < 4; j++) {
                const float* bb = sBc + (kk + q_b) * BST + wn * 32 + j * 8 + col_b;
                bf[j][0] = __float_as_uint(bb[0]);
                bf[j][1] = __float_as_uint(bb[4 * BST]);
            }
#pragma unroll
            for (int i = 0; i < 4; i++)
#pragma unroll
                for (int j = 0; j < 4; j++)
                    mma1688(c[i][j], af[i][0], af[i][1], af[i][2], af[i][3],
                            bf[j][0], bf[j][1]);
        }

        if (ck + 1 < NC) {
            float* dA = sA + (buf ^ 1) * ABUF;
            float* dB = sB + (buf ^ 1) * BBUF;
#pragma unroll
            for (int i = 0; i < 4; i++) {
                float4 av = pa[i];
                av.x = tf32_rna(av.x); av.y = tf32_rna(av.y);
                av.z = tf32_rna(av.z); av.w = tf32_rna(av.w);
                *(float4*)(dA + (a_row + 32 * i) * AST + a_col) = av;
                float4 bv = pb[i];
                bv.x = tf32_rna(bv.x); bv.y = tf32_rna(bv.y);
                bv.z = tf32_rna(bv.z); bv.w = tf32_rna(bv.w);
                *(float4*)(dB + (b_row + 8 * i) * BST + b_col) = bv;
            }
        }
        __syncthreads();
    }

#pragma unroll
    for (int i = 0; i < 4; i++) {
        const int row = m0 + wm * 64 + i * 16 + (lane >> 2);
#pragma unroll
        for (int j = 0; j < 4; j++) {
            const int col = n0 + wn * 32 + j * 8 + (lane & 3) * 2;
            float2 bb = *(const float2*)(bias + col);
            float2 o0, o1;
            o0.x = c[i][j][0] + bb.x;  o0.y = c[i][j][1] + bb.y;
            o1.x = c[i][j][2] + bb.x;  o1.y = c[i][j][3] + bb.y;
            *(float2*)(C + (size_t)row * N + col)       = o0;
            *(float2*)(C + (size_t)(row + 8) * N + col) = o1;
        }
    }
}

// ---------------- RoPE on q,k halves of qkv, in place ------------------------
__global__ void rope_kernel(float* __restrict__ qkv,
                            const float* __restrict__ cosb,
                            const float* __restrict__ sinb)
{
    const int s = blockIdx.x;
    const float* cr = cosb + (size_t)s * HD;
    const float* sr = sinb + (size_t)s * HD;
    float* row = qkv + (size_t)s * H3;

    for (int i = threadIdx.x; i < 2 * NH * (HD / 2); i += blockDim.x) {
        const int which = i / (NH * (HD / 2));
        int jj = i - which * (NH * (HD / 2));
        const int h = jj / (HD / 2);
        const int d = jj - h * (HD / 2);
        float* base = row + which * HID + h * HD;
        float a  = base[d];
        float b  = base[d + HD / 2];
        float c0 = cr[d],          s0 = sr[d];
        float c1 = cr[d + HD / 2], s1 = sr[d + HD / 2];
        base[d]          = a * c0 - b * s0;
        base[d + HD / 2] = b * c1 + a * s1;
    }
}

// =================== tensor-core varlen flash attention =====================
// CTA: 128 q-rows x 1 head, 8 warps (16 rows each), key tiles of 64.
#define BQ 128
#define BK 64
#define KT_ST 72      // sKt [80][72]  (Kt[d][t])
#define V_ST  88      // sV  [64][88]  (V[t][d])
#define P_ST  68      // sP  [128][68] (P[r][t])
#define ATTN_SMEM ((80 * KT_ST + BK * V_ST + BQ * P_ST) * 4)   // 80384 B

__global__ __launch_bounds__(256) void attn_mma_kernel(
    const float* __restrict__ qkv, const int* __restrict__ cu,
    float* __restrict__ out)
{
    extern __shared__ float dsm[];
    float* sKt = dsm;                       // [d][t]
    float* sV  = sKt + 80 * KT_ST;          // [t][d]
    float* sP  = sV  + BK * V_ST;           // [r][t]
    __shared__ int s_cu[NSEQ + 1];

    const int h    = blockIdx.y;
    const int qs0  = blockIdx.x * BQ;
    const int tid  = threadIdx.x;
    const int warp = tid >> 5;
    const int lane = tid & 31;
    const int qr   = lane >> 2;     // 0..7
    const int ql   = lane & 3;      // 0..3

    if (tid <= NSEQ) s_cu[tid] = cu[tid];
    __syncthreads();

    const int row0 = warp * 16 + qr;
    const int row1 = row0 + 8;
    const int s0 = qs0 + row0;
    const int s1 = qs0 + row1;

    int lo0 = 0, hi0 = S_LEN, lo1 = 0, hi1 = S_LEN;
    int blk_lo = 0, blk_hi = S_LEN;
#pragma unroll
    for (int i = 0; i < NSEQ; i++) {
        const int a = s_cu[i], b = s_cu[i + 1];
        if (s0 >= a && s0 < b) { lo0 = a; hi0 = b; }
        if (s1 >= a && s1 < b) { lo1 = a; hi1 = b; }
        if (qs0 >= a && qs0 < b) blk_lo = a;
        if (qs0 + BQ - 1 >= a && qs0 + BQ - 1 < b) blk_hi = b;
    }

    // Q fragments (scaled, tf32)
    uint32_t qf[10][4];
    {
        const float* q0 = qkv + (size_t)s0 * H3 + h * HD;
        const float* q1 = qkv + (size_t)s1 * H3 + h * HD;
#pragma unroll
        for (int kk = 0; kk < 10; kk++) {
            const int d = kk * 8 + ql;
            qf[kk][0] = tf32_rna_u(q0[d] * SCALE);
            qf[kk][1] = tf32_rna_u(q1[d] * SCALE);
            qf[kk][2] = tf32_rna_u(q0[d + 4] * SCALE);
            qf[kk][3] = tf32_rna_u(q1[d + 4] * SCALE);
        }
    }

    float m0 = -1e30f, m1 = -1e30f, l0 = 0.f, l1 = 0.f;
    float of[10][4];
#pragma unroll
    for (int jt = 0; jt < 10; jt++)
#pragma unroll
        for (int v = 0; v < 4; v++) of[jt][v] = 0.f;

    // cooperative load mapping: t = tid>>2 (0..63), dq = tid&3
    const int lt  = tid >> 2;
    const int ldq = tid & 3;

    for (int t0 = blk_lo & ~(BK - 1); t0 < blk_hi; t0 += BK) {
        __syncthreads();   // protect sKt/sV from previous iteration readers
        {
            const float* kp = qkv + (size_t)(t0 + lt) * H3 + HID + h * HD;
            const float* vp = kp + HID;
            float* vd = sV + lt * V_ST;
#pragma unroll
            for (int it = 0; it < 5; it++) {
                const int d = ldq * 4 + it * 16;
                float4 k4 = *(const float4*)(kp + d);
                sKt[(d + 0) * KT_ST + lt] = tf32_rna(k4.x);
                sKt[(d + 1) * KT_ST + lt] = tf32_rna(k4.y);
                sKt[(d + 2) * KT_ST + lt] = tf32_rna(k4.z);
                sKt[(d + 3) * KT_ST + lt] = tf32_rna(k4.w);
                float4 v4 = *(const float4*)(vp + d);
                v4.x = tf32_rna(v4.x); v4.y = tf32_rna(v4.y);
                v4.z = tf32_rna(v4.z); v4.w = tf32_rna(v4.w);
                *(float4*)(vd + d) = v4;
            }
        }
        __syncthreads();

        // S = Q @ K^T  (8 n-tiles of 8 keys, 10 k-steps)
        float sfr[8][4];
#pragma unroll
        for (int j = 0; j < 8; j++) {
            sfr[j][0] = 0.f; sfr[j][1] = 0.f; sfr[j][2] = 0.f; sfr[j][3] = 0.f;
            const float* kb0 = sKt + ql * KT_ST + j * 8 + qr;
#pragma unroll
            for (int kk = 0; kk < 10; kk++) {
                const float* kb = kb0 + kk * 8 * KT_ST;
                mma1688(sfr[j], qf[kk][0], qf[kk][1], qf[kk][2], qf[kk][3],
                        __float_as_uint(kb[0]), __float_as_uint(kb[4 * KT_ST]));
            }
        }

        // mask + row max
        float mx0 = -1e30f, mx1 = -1e30f;
#pragma unroll
        for (int j = 0; j < 8; j++) {
            const int c0 = t0 + j * 8 + 2 * ql;
            const int c1 = c0 + 1;
            if (c0 < lo0 || c0 >= hi0) sfr[j][0] = -1e38f;
            if (c1 < lo0 || c1 >= hi0) sfr[j][1] = -1e38f;
            if (c0 < lo1 || c0 >= hi1) sfr[j][2] = -1e38f;
            if (c1 < lo1 || c1 >= hi1) sfr[j][3] = -1e38f;
            mx0 = fmaxf(mx0, fmaxf(sfr[j][0], sfr[j][1]));
            mx1 = fmaxf(mx1, fmaxf(sfr[j][2], sfr[j][3]));
        }
        mx0 = fmaxf(mx0, __shfl_xor_sync(0xffffffff, mx0, 1));
        mx0 = fmaxf(mx0, __shfl_xor_sync(0xffffffff, mx0, 2));
        mx1 = fmaxf(mx1, __shfl_xor_sync(0xffffffff, mx1, 1));
        mx1 = fmaxf(mx1, __shfl_xor_sync(0xffffffff, mx1, 2));

        const float nm0 = fmaxf(m0, mx0);
        const float nm1 = fmaxf(m1, mx1);
        const float corr0 = __expf(m0 - nm0);
        const float corr1 = __expf(m1 - nm1);
        m0 = nm0; m1 = nm1;

        float ls0 = 0.f, ls1 = 0.f;
        float* p0 = sP + row0 * P_ST + 2 * ql;
        float* p1 = sP + row1 * P_ST + 2 * ql;
#pragma unroll
        for (int j = 0; j < 8; j++) {
            const float e00 = __expf(sfr[j][0] - m0);
            const float e01 = __expf(sfr[j][1] - m0);
            const float e10 = __expf(sfr[j][2] - m1);
            const float e11 = __expf(sfr[j][3] - m1);
            ls0 += e00 + e01;
            ls1 += e10 + e11;
            float2 pv0 = make_float2(tf32_rna(e00), tf32_rna(e01));
            float2 pv1 = make_float2(tf32_rna(e10), tf32_rna(e11));
            *(float2*)(p0 + j * 8) = pv0;
            *(float2*)(p1 + j * 8) = pv1;
        }
        ls0 += __shfl_xor_sync(0xffffffff, ls0, 1);
        ls0 += __shfl_xor_sync(0xffffffff, ls0, 2);
        ls1 += __shfl_xor_sync(0xffffffff, ls1, 1);
        ls1 += __shfl_xor_sync(0xffffffff, ls1, 2);
        l0 = l0 * corr0 + ls0;
        l1 = l1 * corr1 + ls1;

#pragma unroll
        for (int jt = 0; jt < 10; jt++) {
            of[jt][0] *= corr0; of[jt][1] *= corr0;
            of[jt][2] *= corr1; of[jt][3] *= corr1;
        }

        __syncwarp();   // this warp's P rows written only by this warp

        // O += P @ V
        uint32_t af[8][4];
        {
            const float* pb0 = sP + (warp * 16 + qr) * P_ST + ql;
#pragma unroll
            for (int kk = 0; kk < 8; kk++) {
                const float* pb = pb0 + kk * 8;
                af[kk][0] = __float_as_uint(pb[0]);
                af[kk][1] = __float_as_uint(pb[8 * P_ST]);
                af[kk][2] = __float_as_uint(pb[4]);
                af[kk][3] = __float_as_uint(pb[8 * P_ST + 4]);
            }
        }
#pragma unroll
        for (int jt = 0; jt < 10; jt++) {
            const float* vb0 = sV + ql * V_ST + jt * 8 + qr;
#pragma unroll
            for (int kk = 0; kk < 8; kk++) {
                const float* vb = vb0 + kk * 8 * V_ST;
                mma1688(of[jt], af[kk][0], af[kk][1], af[kk][2], af[kk][3],
                        __float_as_uint(vb[0]), __float_as_uint(vb[4 * V_ST]));
            }
        }
    }

    const float inv0 = 1.f / l0;
    const float inv1 = 1.f / l1;
    float* o0 = out + (size_t)s0 * HID + h * HD + 2 * ql;
    float* o1 = out + (size_t)s1 * HID + h * HD + 2 * ql;
#pragma unroll
    for (int jt = 0; jt < 10; jt++) {
        *(float2*)(o0 + jt * 8) = make_float2(of[jt][0] * inv0, of[jt][1] * inv0);
        *(float2*)(o1 + jt * 8) = make_float2(of[jt][2] * inv1, of[jt][3] * inv1);
    }
}

// ---------------------------------------------------------------------------
extern "C" void kernel_launch(void* const* d_in, const int* in_sizes, int n_in,
                              void* d_out, int out_size)
{
    const float* x       = (const float*)d_in[0];
    const int*   cu      = (const int*)  d_in[1];
    const float* cosb    = (const float*)d_in[2];
    const float* sinb    = (const float*)d_in[3];
    const float* w_qkv   = (const float*)d_in[4];
    const float* b_qkv   = (const float*)d_in[5];
    const float* w_proj  = (const float*)d_in[6];
    const float* b_proj  = (const float*)d_in[7];
    float* out = (float*)d_out;

    float* qkv;  cudaGetSymbolAddress((void**)&qkv,  g_qkv);
    float* attn; cudaGetSymbolAddress((void**)&attn, g_attn);

    cudaFuncSetAttribute(gemm_mma_kernel,
                         cudaFuncAttributeMaxDynamicSharedMemorySize, GEMM_SMEM);
    cudaFuncSetAttribute(attn_mma_kernel,
                         cudaFuncAttributeMaxDynamicSharedMemorySize, ATTN_SMEM);

    // 1) qkv = x @ w_qkv + b_qkv    (4096 x 1280 x 3840)
    gemm_mma_kernel<<<dim3(H3 / 128, S_LEN / 128), 256, GEMM_SMEM>>>(
        x, w_qkv, b_qkv, qkv, HID, H3);
    // 2) RoPE on q,k in place
    rope_kernel<<<S_LEN, 128>>>(qkv, cosb, sinb);
    // 3) varlen attention (tensor cores)
    attn_mma_kernel<<<dim3(S_LEN / BQ, NH), 256, ATTN_SMEM>>>(qkv, cu, attn);
    // 4) out = attn @ w_proj + b_proj  (4096 x 1280 x 1280)
    gemm_mma_kernel<<<dim3(HID / 128, S_LEN / 128), 256, GEMM_SMEM>>>(
        attn, w_proj, b_proj, out, HID, HID);
}

// round 5
// speedup vs baseline: 3.5302x; 1.1175x over previous
#include <cuda_runtime.h>
#include <math.h>
#include <cstdint>

#define S_LEN   4096
#define HID     1280
#define H3      3840
#define NH      16
#define HD      80
#define NSEQ    8
#define SCALE   0.11180339887498949f   // 1/sqrt(80)

// ---------------- scratch (device globals; no allocations allowed) ----------
__device__ float g_qkv[(size_t)S_LEN * H3];          // 62.9 MB
__device__ float g_attn[(size_t)S_LEN * HID];        // 21 MB (tf32-rounded)
__device__ float g_xr[(size_t)S_LEN * HID];          // 21 MB (x, tf32-rounded)
__device__ float g_wqkvr[(size_t)HID * H3];          // 19.7 MB
__device__ float g_wprojr[(size_t)HID * HID];        // 6.6 MB

// =================== tf32 helpers ===========================================
__device__ __forceinline__ float tf32_rna(float f) {
    uint32_t u;
    asm("cvt.rna.tf32.f32 %0, %1;" : "=r"(u) : "f"(f));
    return __uint_as_float(u);
}
__device__ __forceinline__ uint32_t tf32_rna_u(float f) {
    uint32_t u;
    asm("cvt.rna.tf32.f32 %0, %1;" : "=r"(u) : "f"(f));
    return u;
}

__device__ __forceinline__ void mma1688(float* d,
                                        uint32_t a0, uint32_t a1, uint32_t a2, uint32_t a3,
                                        uint32_t b0, uint32_t b1) {
    asm volatile(
        "mma.sync.aligned.m16n8k8.row.col.f32.tf32.tf32.f32 "
        "{%0,%1,%2,%3}, {%4,%5,%6,%7}, {%8,%9}, {%0,%1,%2,%3};"
        : "+f"(d[0]), "+f"(d[1]), "+f"(d[2]), "+f"(d[3])
        : "r"(a0), "r"(a1), "r"(a2), "r"(a3), "r"(b0), "r"(b1));
}

__device__ __forceinline__ uint32_t smem_u32(const void* p) {
    uint32_t a;
    asm("{ .reg .u64 t; cvta.to.shared.u64 t, %1; cvt.u32.u64 %0, t; }"
        : "=r"(a) : "l"(p));
    return a;
}
__device__ __forceinline__ void cp_async16(uint32_t dst, const void* src) {
    asm volatile("cp.async.ca.shared.global [%0], [%1], 16;" :: "r"(dst), "l"(src));
}
#define CP_COMMIT() asm volatile("cp.async.commit_group;" ::: "memory")
#define CP_WAIT0()  asm volatile("cp.async.wait_group 0;" ::: "memory")

// =================== tf32 rounding pre-pass =================================
__global__ void round_tf32_kernel(const float* __restrict__ in,
                                  float* __restrict__ out, int n4)
{
    const int i = blockIdx.x * blockDim.x + threadIdx.x;
    if (i < n4) {
        float4 v = ((const float4*)in)[i];
        v.x = tf32_rna(v.x); v.y = tf32_rna(v.y);
        v.z = tf32_rna(v.z); v.w = tf32_rna(v.w);
        ((float4*)out)[i] = v;
    }
}

// =================== tensor-core tf32 GEMM (cp.async pipelined) =============
// C[M,N] = A[M,K] @ W[K,N] + bias. CTA tile 128x128, BK=32, 256 threads.
// A, W must already be tf32-rounded. 2 CTAs/SM target.
#define AST 36
#define BST 136
#define ABUF (128 * AST)
#define BBUF (32 * BST)
#define GEMM_SMEM ((2 * ABUF + 2 * BBUF) * 4)   // 71680 B

__global__ __launch_bounds__(256, 2) void gemm_mma_kernel(
    const float* __restrict__ A, const float* __restrict__ W,
    const float* __restrict__ bias, float* __restrict__ C,
    int K, int N)
{
    extern __shared__ float smem[];
    float* sA = smem;
    float* sB = smem + 2 * ABUF;
    const uint32_t sAu = smem_u32(sA);
    const uint32_t sBu = smem_u32(sB);

    const int tid  = threadIdx.x;
    const int warp = tid >> 5;
    const int lane = tid & 31;
    const int wm = warp >> 2;
    const int wn = warp & 3;
    const int m0 = blockIdx.y * 128;
    const int n0 = blockIdx.x * 128;

    const int r_a   = lane >> 2;
    const int c_a   = lane & 3;
    const int q_b   = lane & 3;
    const int col_b = lane >> 2;

    const int a_row = tid >> 3;
    const int a_col = (tid & 7) * 4;
    const int b_row = tid >> 5;
    const int b_col = (tid & 31) * 4;

    const float* Abase = A + (size_t)(m0 + a_row) * K + a_col;
    const float* Wbase = W + (size_t)b_row * N + n0 + b_col;

    float c[4][4][4];
#pragma unroll
    for (int i = 0; i < 4; i++)
#pragma unroll
        for (int j = 0; j < 4; j++)
#pragma unroll
            for (int v = 0; v < 4; v++) c[i][j][v] = 0.f;

    const int NC = K / 32;

    auto issue_load = [&](int ck, int buf) {
        const int k0 = ck * 32;
        const uint32_t dA = sAu + (uint32_t)(buf * ABUF) * 4;
        const uint32_t dB = sBu + (uint32_t)(buf * BBUF) * 4;
#pragma unroll
        for (int i = 0; i < 4; i++) {
            cp_async16(dA + (uint32_t)((a_row + 32 * i) * AST + a_col) * 4,
                       Abase + (size_t)(32 * i) * K + k0);
            cp_async16(dB + (uint32_t)((b_row + 8 * i) * BST + b_col) * 4,
                       Wbase + (size_t)(k0 + 8 * i) * N);
        }
        CP_COMMIT();
    };

    issue_load(0, 0);
    CP_WAIT0();
    __syncthreads();

    for (int ck = 0; ck < NC; ck++) {
        const int buf = ck & 1;
        if (ck + 1 < NC) issue_load(ck + 1, buf ^ 1);

        const float* sAc = sA + buf * ABUF;
        const float* sBc = sB + buf * BBUF;

#pragma unroll
        for (int t = 0; t < 4; t++) {
            const int kk = t * 8;
            uint32_t af[4][4], bf[4][2];
#pragma unroll
            for (int i = 0; i < 4; i++) {
                const float* ab = sAc + (wm * 64 + i * 16 + r_a) * AST + kk + c_a;
                af[i][0] = __float_as_uint(ab[0]);
                af[i][1] = __float_as_uint(ab[8 * AST]);
                af[i][2] = __float_as_uint(ab[4]);
                af[i][3] = __float_as_uint(ab[8 * AST + 4]);
            }
#pragma unroll
            for (int j = 0; j < 4; j++) {
                const float* bb = sBc + (kk + q_b) * BST + wn * 32 + j * 8 + col_b;
                bf[j][0] = __float_as_uint(bb[0]);
                bf[j][1] = __float_as_uint(bb[4 * BST]);
            }
#pragma unroll
            for (int i = 0; i < 4; i++)
#pragma unroll
                for (int j = 0; j < 4; j++)
                    mma1688(c[i][j], af[i][0], af[i][1], af[i][2], af[i][3],
                            bf[j][0], bf[j][1]);
        }

        if (ck + 1 < NC) CP_WAIT0();
        __syncthreads();
    }

#pragma unroll
    for (int i = 0; i < 4; i++) {
        const int row = m0 + wm * 64 + i * 16 + (lane >> 2);
#pragma unroll
        for (int j = 0; j < 4; j++) {
            const int col = n0 + wn * 32 + j * 8 + (lane & 3) * 2;
            float2 bb = *(const float2*)(bias + col);
            float2 o0, o1;
            o0.x = c[i][j][0] + bb.x;  o0.y = c[i][j][1] + bb.y;
            o1.x = c[i][j][2] + bb.x;  o1.y = c[i][j][3] + bb.y;
            *(float2*)(C + (size_t)row * N + col)       = o0;
            *(float2*)(C + (size_t)(row + 8) * N + col) = o1;
        }
    }
}

// ---------------- RoPE on q,k halves of qkv, in place ------------------------
__global__ void rope_kernel(float* __restrict__ qkv,
                            const float* __restrict__ cosb,
                            const float* __restrict__ sinb)
{
    const int s = blockIdx.x;
    const float* cr = cosb + (size_t)s * HD;
    const float* sr = sinb + (size_t)s * HD;
    float* row = qkv + (size_t)s * H3;

    for (int i = threadIdx.x; i < 2 * NH * (HD / 2); i += blockDim.x) {
        const int which = i / (NH * (HD / 2));
        int jj = i - which * (NH * (HD / 2));
        const int h = jj / (HD / 2);
        const int d = jj - h * (HD / 2);
        float* base = row + which * HID + h * HD;
        float a  = base[d];
        float b  = base[d + HD / 2];
        float c0 = cr[d],          s0 = sr[d];
        float c1 = cr[d + HD / 2], s1 = sr[d + HD / 2];
        base[d]          = a * c0 - b * s0;
        base[d + HD / 2] = b * c1 + a * s1;
    }
}

// =================== tensor-core varlen flash attention =====================
#define BQ 128
#define BK 64
#define KT_ST 72
#define V_ST  88
#define P_ST  68
#define ATTN_SMEM ((80 * KT_ST + BK * V_ST + BQ * P_ST) * 4)

__global__ __launch_bounds__(256) void attn_mma_kernel(
    const float* __restrict__ qkv, const int* __restrict__ cu,
    float* __restrict__ out)
{
    extern __shared__ float dsm[];
    float* sKt = dsm;
    float* sV  = sKt + 80 * KT_ST;
    float* sP  = sV  + BK * V_ST;
    __shared__ int s_cu[NSEQ + 1];

    const int h    = blockIdx.y;
    const int qs0  = blockIdx.x * BQ;
    const int tid  = threadIdx.x;
    const int warp = tid >> 5;
    const int lane = tid & 31;
    const int qr   = lane >> 2;
    const int ql   = lane & 3;

    if (tid <= NSEQ) s_cu[tid] = cu[tid];
    __syncthreads();

    const int row0 = warp * 16 + qr;
    const int row1 = row0 + 8;
    const int s0 = qs0 + row0;
    const int s1 = qs0 + row1;

    int lo0 = 0, hi0 = S_LEN, lo1 = 0, hi1 = S_LEN;
    int blk_lo = 0, blk_hi = S_LEN;
#pragma unroll
    for (int i = 0; i < NSEQ; i++) {
        const int a = s_cu[i], b = s_cu[i + 1];
        if (s0 >= a && s0 < b) { lo0 = a; hi0 = b; }
        if (s1 >= a && s1 < b) { lo1 = a; hi1 = b; }
        if (qs0 >= a && qs0 < b) blk_lo = a;
        if (qs0 + BQ - 1 >= a && qs0 + BQ - 1 < b) blk_hi = b;
    }

    uint32_t qf[10][4];
    {
        const float* q0 = qkv + (size_t)s0 * H3 + h * HD;
        const float* q1 = qkv + (size_t)s1 * H3 + h * HD;
#pragma unroll
        for (int kk = 0; kk < 10; kk++) {
            const int d = kk * 8 + ql;
            qf[kk][0] = tf32_rna_u(q0[d] * SCALE);
            qf[kk][1] = tf32_rna_u(q1[d] * SCALE);
            qf[kk][2] = tf32_rna_u(q0[d + 4] * SCALE);
            qf[kk][3] = tf32_rna_u(q1[d + 4] * SCALE);
        }
    }

    float m0 = -1e30f, m1 = -1e30f, l0 = 0.f, l1 = 0.f;
    float of[10][4];
#pragma unroll
    for (int jt = 0; jt < 10; jt++)
#pragma unroll
        for (int v = 0; v < 4; v++) of[jt][v] = 0.f;

    const int lt  = tid >> 2;
    const int ldq = tid & 3;

    for (int t0 = blk_lo & ~(BK - 1); t0 < blk_hi; t0 += BK) {
        __syncthreads();
        {
            const float* kp = qkv + (size_t)(t0 + lt) * H3 + HID + h * HD;
            const float* vp = kp + HID;
            float* vd = sV + lt * V_ST;
#pragma unroll
            for (int it = 0; it < 5; it++) {
                const int d = ldq * 4 + it * 16;
                float4 k4 = *(const float4*)(kp + d);
                sKt[(d + 0) * KT_ST + lt] = tf32_rna(k4.x);
                sKt[(d + 1) * KT_ST + lt] = tf32_rna(k4.y);
                sKt[(d + 2) * KT_ST + lt] = tf32_rna(k4.z);
                sKt[(d + 3) * KT_ST + lt] = tf32_rna(k4.w);
                float4 v4 = *(const float4*)(vp + d);
                v4.x = tf32_rna(v4.x); v4.y = tf32_rna(v4.y);
                v4.z = tf32_rna(v4.z); v4.w = tf32_rna(v4.w);
                *(float4*)(vd + d) = v4;
            }
        }
        __syncthreads();

        float sfr[8][4];
#pragma unroll
        for (int j = 0; j < 8; j++) {
            sfr[j][0] = 0.f; sfr[j][1] = 0.f; sfr[j][2] = 0.f; sfr[j][3] = 0.f;
            const float* kb0 = sKt + ql * KT_ST + j * 8 + qr;
#pragma unroll
            for (int kk = 0; kk < 10; kk++) {
                const float* kb = kb0 + kk * 8 * KT_ST;
                mma1688(sfr[j], qf[kk][0], qf[kk][1], qf[kk][2], qf[kk][3],
                        __float_as_uint(kb[0]), __float_as_uint(kb[4 * KT_ST]));
            }
        }

        float mx0 = -1e30f, mx1 = -1e30f;
#pragma unroll
        for (int j = 0; j < 8; j++) {
            const int c0 = t0 + j * 8 + 2 * ql;
            const int c1 = c0 + 1;
            if (c0 < lo0 || c0 >= hi0) sfr[j][0] = -1e38f;
            if (c1 < lo0 || c1 >= hi0) sfr[j][1] = -1e38f;
            if (c0 < lo1 || c0 >= hi1) sfr[j][2] = -1e38f;
            if (c1 < lo1 || c1 >= hi1) sfr[j][3] = -1e38f;
            mx0 = fmaxf(mx0, fmaxf(sfr[j][0], sfr[j][1]));
            mx1 = fmaxf(mx1, fmaxf(sfr[j][2], sfr[j][3]));
        }
        mx0 = fmaxf(mx0, __shfl_xor_sync(0xffffffff, mx0, 1));
        mx0 = fmaxf(mx0, __shfl_xor_sync(0xffffffff, mx0, 2));
        mx1 = fmaxf(mx1, __shfl_xor_sync(0xffffffff, mx1, 1));
        mx1 = fmaxf(mx1, __shfl_xor_sync(0xffffffff, mx1, 2));

        const float nm0 = fmaxf(m0, mx0);
        const float nm1 = fmaxf(m1, mx1);
        const float corr0 = __expf(m0 - nm0);
        const float corr1 = __expf(m1 - nm1);
        m0 = nm0; m1 = nm1;

        float ls0 = 0.f, ls1 = 0.f;
        float* p0 = sP + row0 * P_ST + 2 * ql;
        float* p1 = sP + row1 * P_ST + 2 * ql;
#pragma unroll
        for (int j = 0; j < 8; j++) {
            const float e00 = __expf(sfr[j][0] - m0);
            const float e01 = __expf(sfr[j][1] - m0);
            const float e10 = __expf(sfr[j][2] - m1);
            const float e11 = __expf(sfr[j][3] - m1);
            ls0 += e00 + e01;
            ls1 += e10 + e11;
            *(float2*)(p0 + j * 8) = make_float2(tf32_rna(e00), tf32_rna(e01));
            *(float2*)(p1 + j * 8) = make_float2(tf32_rna(e10), tf32_rna(e11));
        }
        ls0 += __shfl_xor_sync(0xffffffff, ls0, 1);
        ls0 += __shfl_xor_sync(0xffffffff, ls0, 2);
        ls1 += __shfl_xor_sync(0xffffffff, ls1, 1);
        ls1 += __shfl_xor_sync(0xffffffff, ls1, 2);
        l0 = l0 * corr0 + ls0;
        l1 = l1 * corr1 + ls1;

#pragma unroll
        for (int jt = 0; jt < 10; jt++) {
            of[jt][0] *= corr0; of[jt][1] *= corr0;
            of[jt][2] *= corr1; of[jt][3] *= corr1;
        }

        __syncwarp();

        uint32_t af[8][4];
        {
            const float* pb0 = sP + (warp * 16 + qr) * P_ST + ql;
#pragma unroll
            for (int kk = 0; kk < 8; kk++) {
                const float* pb = pb0 + kk * 8;
                af[kk][0] = __float_as_uint(pb[0]);
                af[kk][1] = __float_as_uint(pb[8 * P_ST]);
                af[kk][2] = __float_as_uint(pb[4]);
                af[kk][3] = __float_as_uint(pb[8 * P_ST + 4]);
            }
        }
#pragma unroll
        for (int jt = 0; jt < 10; jt++) {
            const float* vb0 = sV + ql * V_ST + jt * 8 + qr;
#pragma unroll
            for (int kk = 0; kk < 8; kk++) {
                const float* vb = vb0 + kk * 8 * V_ST;
                mma1688(of[jt], af[kk][0], af[kk][1], af[kk][2], af[kk][3],
                        __float_as_uint(vb[0]), __float_as_uint(vb[4 * V_ST]));
            }
        }
    }

    // store tf32-rounded so the proj GEMM input is exact tf32
    const float inv0 = 1.f / l0;
    const float inv1 = 1.f / l1;
    float* o0 = out + (size_t)s0 * HID + h * HD + 2 * ql;
    float* o1 = out + (size_t)s1 * HID + h * HD + 2 * ql;
#pragma unroll
    for (int jt = 0; jt < 10; jt++) {
        *(float2*)(o0 + jt * 8) = make_float2(tf32_rna(of[jt][0] * inv0),
                                              tf32_rna(of[jt][1] * inv0));
        *(float2*)(o1 + jt * 8) = make_float2(tf32_rna(of[jt][2] * inv1),
                                              tf32_rna(of[jt][3] * inv1));
    }
}

// ---------------------------------------------------------------------------
extern "C" void kernel_launch(void* const* d_in, const int* in_sizes, int n_in,
                              void* d_out, int out_size)
{
    const float* x       = (const float*)d_in[0];
    const int*   cu      = (const int*)  d_in[1];
    const float* cosb    = (const float*)d_in[2];
    const float* sinb    = (const float*)d_in[3];
    const float* w_qkv   = (const float*)d_in[4];
    const float* b_qkv   = (const float*)d_in[5];
    const float* w_proj  = (const float*)d_in[6];
    const float* b_proj  = (const float*)d_in[7];
    float* out = (float*)d_out;

    float* qkv;    cudaGetSymbolAddress((void**)&qkv,    g_qkv);
    float* attn;   cudaGetSymbolAddress((void**)&attn,   g_attn);
    float* xr;     cudaGetSymbolAddress((void**)&xr,     g_xr);
    float* wqkvr;  cudaGetSymbolAddress((void**)&wqkvr,  g_wqkvr);
    float* wprojr; cudaGetSymbolAddress((void**)&wprojr, g_wprojr);

    cudaFuncSetAttribute(gemm_mma_kernel,
                         cudaFuncAttributeMaxDynamicSharedMemorySize, GEMM_SMEM);
    cudaFuncSetAttribute(attn_mma_kernel,
                         cudaFuncAttributeMaxDynamicSharedMemorySize, ATTN_SMEM);

    // 0) tf32-round GEMM operands
    {
        const int nt = 256;
        round_tf32_kernel<<<(S_LEN * HID / 4 + nt - 1) / nt, nt>>>(x, xr, S_LEN * HID / 4);
        round_tf32_kernel<<<(HID * H3 / 4 + nt - 1) / nt, nt>>>(w_qkv, wqkvr, HID * H3 / 4);
        round_tf32_kernel<<<(HID * HID / 4 + nt - 1) / nt, nt>>>(w_proj, wprojr, HID * HID / 4);
    }
    // 1) qkv = x @ w_qkv + b_qkv
    gemm_mma_kernel<<<dim3(H3 / 128, S_LEN / 128), 256, GEMM_SMEM>>>(
        xr, wqkvr, b_qkv, qkv, HID, H3);
    // 2) RoPE
    rope_kernel<<<S_LEN, 128>>>(qkv, cosb, sinb);
    // 3) attention
    attn_mma_kernel<<<dim3(S_LEN / BQ, NH), 256, ATTN_SMEM>>>(qkv, cu, attn);
    // 4) out = attn @ w_proj + b_proj
    gemm_mma_kernel<<<dim3(HID / 128, S_LEN / 128), 256, GEMM_SMEM>>>(
        attn, wprojr, b_proj, out, HID, HID);
}

// round 6
// speedup vs baseline: 3.6771x; 1.0416x over previous
#include <cuda_runtime.h>
#include <math.h>
#include <cstdint>

#define S_LEN   4096
#define HID     1280
#define H3      3840
#define NH      16
#define HD      80
#define NSEQ    8
#define SCALE   0.11180339887498949f   // 1/sqrt(80)

// ---------------- scratch (device globals; no allocations allowed) ----------
__device__ float g_qkv[(size_t)S_LEN * H3];          // 62.9 MB
__device__ float g_attn[(size_t)S_LEN * HID];        // 21 MB (tf32-rounded)
__device__ float g_xr[(size_t)S_LEN * HID];          // 21 MB (x, tf32-rounded)
__device__ float g_wqkvr[(size_t)HID * H3];          // 19.7 MB
__device__ float g_wprojr[(size_t)HID * HID];        // 6.6 MB

// =================== tf32 helpers ===========================================
__device__ __forceinline__ float tf32_rna(float f) {
    uint32_t u;
    asm("cvt.rna.tf32.f32 %0, %1;" : "=r"(u) : "f"(f));
    return __uint_as_float(u);
}
__device__ __forceinline__ uint32_t tf32_rna_u(float f) {
    uint32_t u;
    asm("cvt.rna.tf32.f32 %0, %1;" : "=r"(u) : "f"(f));
    return u;
}

__device__ __forceinline__ void mma1688(float* d,
                                        uint32_t a0, uint32_t a1, uint32_t a2, uint32_t a3,
                                        uint32_t b0, uint32_t b1) {
    asm volatile(
        "mma.sync.aligned.m16n8k8.row.col.f32.tf32.tf32.f32 "
        "{%0,%1,%2,%3}, {%4,%5,%6,%7}, {%8,%9}, {%0,%1,%2,%3};"
        : "+f"(d[0]), "+f"(d[1]), "+f"(d[2]), "+f"(d[3])
        : "r"(a0), "r"(a1), "r"(a2), "r"(a3), "r"(b0), "r"(b1));
}

__device__ __forceinline__ uint32_t smem_u32(const void* p) {
    uint32_t a;
    asm("{ .reg .u64 t; cvta.to.shared.u64 t, %1; cvt.u32.u64 %0, t; }"
        : "=r"(a) : "l"(p));
    return a;
}
__device__ __forceinline__ void cp_async16(uint32_t dst, const void* src) {
    asm volatile("cp.async.ca.shared.global [%0], [%1], 16;" :: "r"(dst), "l"(src));
}
#define CP_COMMIT() asm volatile("cp.async.commit_group;" ::: "memory")
#define CP_WAIT0()  asm volatile("cp.async.wait_group 0;" ::: "memory")

// =================== tf32 rounding pre-pass =================================
__global__ void round_tf32_kernel(const float* __restrict__ in,
                                  float* __restrict__ out, int n4)
{
    const int i = blockIdx.x * blockDim.x + threadIdx.x;
    if (i < n4) {
        float4 v = ((const float4*)in)[i];
        v.x = tf32_rna(v.x); v.y = tf32_rna(v.y);
        v.z = tf32_rna(v.z); v.w = tf32_rna(v.w);
        ((float4*)out)[i] = v;
    }
}

// =================== tensor-core tf32 GEMM (cp.async pipelined) =============
// C[M,N] = A[M,K] @ W[K,N] + bias. CTA tile 128x128, BK=32, 128 threads.
// 4 warps in 2x2, warp tile 64x64 (4 m-tiles x 8 n-tiles of m16n8k8).
// A, W must already be tf32-rounded.
#define AST 36
#define BST 136
#define ABUF (128 * AST)
#define BBUF (32 * BST)
#define GEMM_SMEM ((2 * ABUF + 2 * BBUF) * 4)   // 71680 B

__global__ __launch_bounds__(128, 2) void gemm_mma_kernel(
    const float* __restrict__ A, const float* __restrict__ W,
    const float* __restrict__ bias, float* __restrict__ C,
    int K, int N)
{
    extern __shared__ float smem[];
    float* sA = smem;
    float* sB = smem + 2 * ABUF;
    const uint32_t sAu = smem_u32(sA);
    const uint32_t sBu = smem_u32(sB);

    const int tid  = threadIdx.x;
    const int warp = tid >> 5;
    const int lane = tid & 31;
    const int wm = warp >> 1;           // 0..1
    const int wn = warp & 1;            // 0..1
    const int m0 = blockIdx.y * 128;
    const int n0 = blockIdx.x * 128;

    const int r_a   = lane >> 2;
    const int c_a   = lane & 3;
    const int q_b   = lane & 3;
    const int col_b = lane >> 2;

    // gmem loader mapping (128 threads)
    const int a_row = tid >> 3;          // 0..15
    const int a_col = (tid & 7) * 4;     // 0..28
    const int b_row = tid >> 5;          // 0..3
    const int b_col = (tid & 31) * 4;    // 0..124

    const float* Abase = A + (size_t)(m0 + a_row) * K + a_col;
    const float* Wbase = W + (size_t)b_row * N + n0 + b_col;

    float c[4][8][4];
#pragma unroll
    for (int i = 0; i < 4; i++)
#pragma unroll
        for (int j = 0; j < 8; j++)
#pragma unroll
            for (int v = 0; v < 4; v++) c[i][j][v] = 0.f;

    const int NC = K / 32;

    auto issue_load = [&](int ck, int buf) {
        const int k0 = ck * 32;
        const uint32_t dA = sAu + (uint32_t)(buf * ABUF) * 4;
        const uint32_t dB = sBu + (uint32_t)(buf * BBUF) * 4;
#pragma unroll
        for (int i = 0; i < 8; i++) {
            cp_async16(dA + (uint32_t)((a_row + 16 * i) * AST + a_col) * 4,
                       Abase + (size_t)(16 * i) * K + k0);
            cp_async16(dB + (uint32_t)((b_row + 4 * i) * BST + b_col) * 4,
                       Wbase + (size_t)(k0 + b_row + 4 * i - b_row) * N + (size_t)0
                       + (size_t)0);
        }
        CP_COMMIT();
    };
    // NOTE: lambda above needs the correct W row address; rewritten explicitly:
    auto issue_load2 = [&](int ck, int buf) {
        const int k0 = ck * 32;
        const uint32_t dA = sAu + (uint32_t)(buf * ABUF) * 4;
        const uint32_t dB = sBu + (uint32_t)(buf * BBUF) * 4;
#pragma unroll
        for (int i = 0; i < 8; i++) {
            cp_async16(dA + (uint32_t)((a_row + 16 * i) * AST + a_col) * 4,
                       Abase + (size_t)(16 * i) * K + k0);
            cp_async16(dB + (uint32_t)((b_row + 4 * i) * BST + b_col) * 4,
                       W + (size_t)(k0 + b_row + 4 * i) * N + n0 + b_col);
        }
        CP_COMMIT();
    };
    (void)issue_load;

    issue_load2(0, 0);
    CP_WAIT0();
    __syncthreads();

    for (int ck = 0; ck < NC; ck++) {
        const int buf = ck & 1;
        if (ck + 1 < NC) issue_load2(ck + 1, buf ^ 1);

        const float* sAc = sA + buf * ABUF;
        const float* sBc = sB + buf * BBUF;

#pragma unroll
        for (int t = 0; t < 4; t++) {
            const int kk = t * 8;
            uint32_t af[4][4], bf[8][2];
#pragma unroll
            for (int i = 0; i < 4; i++) {
                const float* ab = sAc + (wm * 64 + i * 16 + r_a) * AST + kk + c_a;
                af[i][0] = __float_as_uint(ab[0]);
                af[i][1] = __float_as_uint(ab[8 * AST]);
                af[i][2] = __float_as_uint(ab[4]);
                af[i][3] = __float_as_uint(ab[8 * AST + 4]);
            }
#pragma unroll
            for (int j = 0; j < 8; j++) {
                const float* bb = sBc + (kk + q_b) * BST + wn * 64 + j * 8 + col_b;
                bf[j][0] = __float_as_uint(bb[0]);
                bf[j][1] = __float_as_uint(bb[4 * BST]);
            }
#pragma unroll
            for (int i = 0; i < 4; i++)
#pragma unroll
                for (int j = 0; j < 8; j++)
                    mma1688(c[i][j], af[i][0], af[i][1], af[i][2], af[i][3],
                            bf[j][0], bf[j][1]);
        }

        if (ck + 1 < NC) CP_WAIT0();
        __syncthreads();
    }

#pragma unroll
    for (int i = 0; i < 4; i++) {
        const int row = m0 + wm * 64 + i * 16 + (lane >> 2);
#pragma unroll
        for (int j = 0; j < 8; j++) {
            const int col = n0 + wn * 64 + j * 8 + (lane & 3) * 2;
            float2 bb = *(const float2*)(bias + col);
            float2 o0, o1;
            o0.x = c[i][j][0] + bb.x;  o0.y = c[i][j][1] + bb.y;
            o1.x = c[i][j][2] + bb.x;  o1.y = c[i][j][3] + bb.y;
            *(float2*)(C + (size_t)row * N + col)       = o0;
            *(float2*)(C + (size_t)(row + 8) * N + col) = o1;
        }
    }
}

// ---------------- RoPE on q,k halves of qkv, in place ------------------------
__global__ void rope_kernel(float* __restrict__ qkv,
                            const float* __restrict__ cosb,
                            const float* __restrict__ sinb)
{
    const int s = blockIdx.x;
    const float* cr = cosb + (size_t)s * HD;
    const float* sr = sinb + (size_t)s * HD;
    float* row = qkv + (size_t)s * H3;

    for (int i = threadIdx.x; i < 2 * NH * (HD / 2); i += blockDim.x) {
        const int which = i / (NH * (HD / 2));
        int jj = i - which * (NH * (HD / 2));
        const int h = jj / (HD / 2);
        const int d = jj - h * (HD / 2);
        float* base = row + which * HID + h * HD;
        float a  = base[d];
        float b  = base[d + HD / 2];
        float c0 = cr[d],          s0 = sr[d];
        float c1 = cr[d + HD / 2], s1 = sr[d + HD / 2];
        base[d]          = a * c0 - b * s0;
        base[d + HD / 2] = b * c1 + a * s1;
    }
}

// =================== tensor-core varlen flash attention =====================
#define BQ 128
#define BK 64
#define KT_ST 72
#define V_ST  88
#define P_ST  68
#define ATTN_SMEM ((80 * KT_ST + BK * V_ST + BQ * P_ST) * 4)

__global__ __launch_bounds__(256) void attn_mma_kernel(
    const float* __restrict__ qkv, const int* __restrict__ cu,
    float* __restrict__ out)
{
    extern __shared__ float dsm[];
    float* sKt = dsm;
    float* sV  = sKt + 80 * KT_ST;
    float* sP  = sV  + BK * V_ST;
    __shared__ int s_cu[NSEQ + 1];

    const int h    = blockIdx.y;
    const int qs0  = blockIdx.x * BQ;
    const int tid  = threadIdx.x;
    const int warp = tid >> 5;
    const int lane = tid & 31;
    const int qr   = lane >> 2;
    const int ql   = lane & 3;

    if (tid <= NSEQ) s_cu[tid] = cu[tid];
    __syncthreads();

    const int row0 = warp * 16 + qr;
    const int row1 = row0 + 8;
    const int s0 = qs0 + row0;
    const int s1 = qs0 + row1;

    int lo0 = 0, hi0 = S_LEN, lo1 = 0, hi1 = S_LEN;
    int blk_lo = 0, blk_hi = S_LEN;
#pragma unroll
    for (int i = 0; i < NSEQ; i++) {
        const int a = s_cu[i], b = s_cu[i + 1];
        if (s0 >= a && s0 < b) { lo0 = a; hi0 = b; }
        if (s1 >= a && s1 < b) { lo1 = a; hi1 = b; }
        if (qs0 >= a && qs0 < b) blk_lo = a;
        if (qs0 + BQ - 1 >= a && qs0 + BQ - 1 < b) blk_hi = b;
    }

    uint32_t qf[10][4];
    {
        const float* q0 = qkv + (size_t)s0 * H3 + h * HD;
        const float* q1 = qkv + (size_t)s1 * H3 + h * HD;
#pragma unroll
        for (int kk = 0; kk < 10; kk++) {
            const int d = kk * 8 + ql;
            qf[kk][0] = tf32_rna_u(q0[d] * SCALE);
            qf[kk][1] = tf32_rna_u(q1[d] * SCALE);
            qf[kk][2] = tf32_rna_u(q0[d + 4] * SCALE);
            qf[kk][3] = tf32_rna_u(q1[d + 4] * SCALE);
        }
    }

    float m0 = -1e30f, m1 = -1e30f, l0 = 0.f, l1 = 0.f;
    float of[10][4];
#pragma unroll
    for (int jt = 0; jt < 10; jt++)
#pragma unroll
        for (int v = 0; v < 4; v++) of[jt][v] = 0.f;

    const int lt  = tid >> 2;
    const int ldq = tid & 3;

    for (int t0 = blk_lo & ~(BK - 1); t0 < blk_hi; t0 += BK) {
        __syncthreads();
        {
            const float* kp = qkv + (size_t)(t0 + lt) * H3 + HID + h * HD;
            const float* vp = kp + HID;
            float* vd = sV + lt * V_ST;
#pragma unroll
            for (int it = 0; it < 5; it++) {
                const int d = ldq * 4 + it * 16;
                float4 k4 = *(const float4*)(kp + d);
                sKt[(d + 0) * KT_ST + lt] = tf32_rna(k4.x);
                sKt[(d + 1) * KT_ST + lt] = tf32_rna(k4.y);
                sKt[(d + 2) * KT_ST + lt] = tf32_rna(k4.z);
                sKt[(d + 3) * KT_ST + lt] = tf32_rna(k4.w);
                float4 v4 = *(const float4*)(vp + d);
                v4.x = tf32_rna(v4.x); v4.y = tf32_rna(v4.y);
                v4.z = tf32_rna(v4.z); v4.w = tf32_rna(v4.w);
                *(float4*)(vd + d) = v4;
            }
        }
        __syncthreads();

        float sfr[8][4];
#pragma unroll
        for (int j = 0; j < 8; j++) {
            sfr[j][0] = 0.f; sfr[j][1] = 0.f; sfr[j][2] = 0.f; sfr[j][3] = 0.f;
            const float* kb0 = sKt + ql * KT_ST + j * 8 + qr;
#pragma unroll
            for (int kk = 0; kk < 10; kk++) {
                const float* kb = kb0 + kk * 8 * KT_ST;
                mma1688(sfr[j], qf[kk][0], qf[kk][1], qf[kk][2], qf[kk][3],
                        __float_as_uint(kb[0]), __float_as_uint(kb[4 * KT_ST]));
            }
        }

        float mx0 = -1e30f, mx1 = -1e30f;
#pragma unroll
        for (int j = 0; j < 8; j++) {
            const int c0 = t0 + j * 8 + 2 * ql;
            const int c1 = c0 + 1;
            if (c0 < lo0 || c0 >= hi0) sfr[j][0] = -1e38f;
            if (c1 < lo0 || c1 >= hi0) sfr[j][1] = -1e38f;
            if (c0 < lo1 || c0 >= hi1) sfr[j][2] = -1e38f;
            if (c1 < lo1 || c1 >= hi1) sfr[j][3] = -1e38f;
            mx0 = fmaxf(mx0, fmaxf(sfr[j][0], sfr[j][1]));
            mx1 = fmaxf(mx1, fmaxf(sfr[j][2], sfr[j][3]));
        }
        mx0 = fmaxf(mx0, __shfl_xor_sync(0xffffffff, mx0, 1));
        mx0 = fmaxf(mx0, __shfl_xor_sync(0xffffffff, mx0, 2));
        mx1 = fmaxf(mx1, __shfl_xor_sync(0xffffffff, mx1, 1));
        mx1 = fmaxf(mx1, __shfl_xor_sync(0xffffffff, mx1, 2));

        const float nm0 = fmaxf(m0, mx0);
        const float nm1 = fmaxf(m1, mx1);
        const float corr0 = __expf(m0 - nm0);
        const float corr1 = __expf(m1 - nm1);
        m0 = nm0; m1 = nm1;

        float ls0 = 0.f, ls1 = 0.f;
        float* p0 = sP + row0 * P_ST + 2 * ql;
        float* p1 = sP + row1 * P_ST + 2 * ql;
#pragma unroll
        for (int j = 0; j < 8; j++) {
            const float e00 = __expf(sfr[j][0] - m0);
            const float e01 = __expf(sfr[j][1] - m0);
            const float e10 = __expf(sfr[j][2] - m1);
            const float e11 = __expf(sfr[j][3] - m1);
            ls0 += e00 + e01;
            ls1 += e10 + e11;
            *(float2*)(p0 + j * 8) = make_float2(tf32_rna(e00), tf32_rna(e01));
            *(float2*)(p1 + j * 8) = make_float2(tf32_rna(e10), tf32_rna(e11));
        }
        ls0 += __shfl_xor_sync(0xffffffff, ls0, 1);
        ls0 += __shfl_xor_sync(0xffffffff, ls0, 2);
        ls1 += __shfl_xor_sync(0xffffffff, ls1, 1);
        ls1 += __shfl_xor_sync(0xffffffff, ls1, 2);
        l0 = l0 * corr0 + ls0;
        l1 = l1 * corr1 + ls1;

#pragma unroll
        for (int jt = 0; jt < 10; jt++) {
            of[jt][0] *= corr0; of[jt][1] *= corr0;
            of[jt][2] *= corr1; of[jt][3] *= corr1;
        }

        __syncwarp();

        uint32_t af[8][4];
        {
            const float* pb0 = sP + (warp * 16 + qr) * P_ST + ql;
#pragma unroll
            for (int kk = 0; kk < 8; kk++) {
                const float* pb = pb0 + kk * 8;
                af[kk][0] = __float_as_uint(pb[0]);
                af[kk][1] = __float_as_uint(pb[8 * P_ST]);
                af[kk][2] = __float_as_uint(pb[4]);
                af[kk][3] = __float_as_uint(pb[8 * P_ST + 4]);
            }
        }
#pragma unroll
        for (int jt = 0; jt < 10; jt++) {
            const float* vb0 = sV + ql * V_ST + jt * 8 + qr;
#pragma unroll
            for (int kk = 0; kk < 8; kk++) {
                const float* vb = vb0 + kk * 8 * V_ST;
                mma1688(of[jt], af[kk][0], af[kk][1], af[kk][2], af[kk][3],
                        __float_as_uint(vb[0]), __float_as_uint(vb[4 * V_ST]));
            }
        }
    }

    const float inv0 = 1.f / l0;
    const float inv1 = 1.f / l1;
    float* o0 = out + (size_t)s0 * HID + h * HD + 2 * ql;
    float* o1 = out + (size_t)s1 * HID + h * HD + 2 * ql;
#pragma unroll
    for (int jt = 0; jt < 10; jt++) {
        *(float2*)(o0 + jt * 8) = make_float2(tf32_rna(of[jt][0] * inv0),
                                              tf32_rna(of[jt][1] * inv0));
        *(float2*)(o1 + jt * 8) = make_float2(tf32_rna(of[jt][2] * inv1),
                                              tf32_rna(of[jt][3] * inv1));
    }
}

// ---------------------------------------------------------------------------
extern "C" void kernel_launch(void* const* d_in, const int* in_sizes, int n_in,
                              void* d_out, int out_size)
{
    const float* x       = (const float*)d_in[0];
    const int*   cu      = (const int*)  d_in[1];
    const float* cosb    = (const float*)d_in[2];
    const float* sinb    = (const float*)d_in[3];
    const float* w_qkv   = (const float*)d_in[4];
    const float* b_qkv   = (const float*)d_in[5];
    const float* w_proj  = (const float*)d_in[6];
    const float* b_proj  = (const float*)d_in[7];
    float* out = (float*)d_out;

    float* qkv;    cudaGetSymbolAddress((void**)&qkv,    g_qkv);
    float* attn;   cudaGetSymbolAddress((void**)&attn,   g_attn);
    float* xr;     cudaGetSymbolAddress((void**)&xr,     g_xr);
    float* wqkvr;  cudaGetSymbolAddress((void**)&wqkvr,  g_wqkvr);
    float* wprojr; cudaGetSymbolAddress((void**)&wprojr, g_wprojr);

    cudaFuncSetAttribute(gemm_mma_kernel,
                         cudaFuncAttributeMaxDynamicSharedMemorySize, GEMM_SMEM);
    cudaFuncSetAttribute(attn_mma_kernel,
                         cudaFuncAttributeMaxDynamicSharedMemorySize, ATTN_SMEM);

    // 0) tf32-round GEMM operands
    {
        const int nt = 256;
        round_tf32_kernel<<<(S_LEN * HID / 4 + nt - 1) / nt, nt>>>(x, xr, S_LEN * HID / 4);
        round_tf32_kernel<<<(HID * H3 / 4 + nt - 1) / nt, nt>>>(w_qkv, wqkvr, HID * H3 / 4);
        round_tf32_kernel<<<(HID * HID / 4 + nt - 1) / nt, nt>>>(w_proj, wprojr, HID * HID / 4);
    }
    // 1) qkv = x @ w_qkv + b_qkv
    gemm_mma_kernel<<<dim3(H3 / 128, S_LEN / 128), 128, GEMM_SMEM>>>(
        xr, wqkvr, b_qkv, qkv, HID, H3);
    // 2) RoPE
    rope_kernel<<<S_LEN, 128>>>(qkv, cosb, sinb);
    // 3) attention
    attn_mma_kernel<<<dim3(S_LEN / BQ, NH), 256, ATTN_SMEM>>>(qkv, cu, attn);
    // 4) out = attn @ w_proj + b_proj
    gemm_mma_kernel<<<dim3(HID / 128, S_LEN / 128), 128, GEMM_SMEM>>>(
        attn, wprojr, b_proj, out, HID, HID);
}